// round 5
// baseline (speedup 1.0000x reference)
#include <cuda_runtime.h>

#define G 128
#define TPB 256
#define T_STEPS 220

// Seqlock exchange buffers: {val0, val1, seq, seq} per CTA (bit-exact u32 lanes).
__device__ float4 g_h0buf[G];
__device__ float4 g_h1buf[G];
__device__ float4 g_h2buf[G];
__device__ float4 g_rbuf[G];

__device__ __forceinline__ void ldv4(const float4* p, float& a, float& b,
                                     unsigned& s0, unsigned& s1) {
    unsigned x, y;
    asm volatile("ld.volatile.global.v4.b32 {%0,%1,%2,%3}, [%4];"
                 : "=r"(x), "=r"(y), "=r"(s0), "=r"(s1) : "l"(p));
    a = __uint_as_float(x);
    b = __uint_as_float(y);
}
__device__ __forceinline__ void stv4(float4* p, float a, float b, unsigned s) {
    asm volatile("st.volatile.global.v4.b32 [%0], {%1,%2,%3,%4};"
                 :: "l"(p), "r"(__float_as_uint(a)), "r"(__float_as_uint(b)),
                    "r"(s), "r"(s));
}
__device__ __forceinline__ float wreduce(float v) {
    v += __shfl_xor_sync(0xffffffffu, v, 16);
    v += __shfl_xor_sync(0xffffffffu, v, 8);
    v += __shfl_xor_sync(0xffffffffu, v, 4);
    v += __shfl_xor_sync(0xffffffffu, v, 2);
    v += __shfl_xor_sync(0xffffffffu, v, 1);
    return v;
}
__device__ __forceinline__ float sigf(float x) { return 1.0f / (1.0f + expf(-x)); }

__device__ __forceinline__ float dot256(const float* w, const float* x, int lane) {
    const float4* w4 = (const float4*)w;
    const float4* x4 = (const float4*)x;
    float s = 0.f;
#pragma unroll
    for (int i = 0; i < 2; i++) {
        float4 a = w4[i * 32 + lane], b = x4[i * 32 + lane];
        s += a.x * b.x + a.y * b.y + a.z * b.z + a.w * b.w;
    }
    return s;
}
// Warps 0-3 poll all 128 slices (one LDG.128 each), scatter into SMEM vector.
__device__ __forceinline__ void gather(const float4* buf, float* dst,
                                       unsigned seq, int wid, int lane) {
    if (wid < 4) {
        int s = wid * 32 + lane;
        float a, b; unsigned s0, s1;
        for (;;) {
            ldv4(buf + s, a, b, s0, s1);
            if (__all_sync(0xffffffffu, (s0 == seq) & (s1 == seq))) break;
        }
        dst[2 * s] = a;
        dst[2 * s + 1] = b;
    }
    __syncthreads();
}

// SMEM layout (floats)
#define OFF_L0W   0       // 8 x 512  layer0 [Wih(:,0:256) | Whh]
#define OFF_WH1   4096    // 8 x 256
#define OFF_WH2   6144    // 8 x 256
#define OFF_WI1   8192    // 8 x 256
#define OFF_WI2   10240   // 8 x 256
#define OFF_W1R   12288   // 2 x 256
#define OFF_W2S   12800   // 33 x 256
#define OFF_EMB   21248   // 33 x 256
#define OFF_H0S   29696   // 256
#define OFF_H1S   29952
#define OFF_H2S   30208
#define OFF_RS    30464
#define OFF_GA    30720   // 8
#define OFF_GB    30728
#define OFF_GC    30736
#define OFF_GT    30744
#define OFF_GD    30752   // 4
#define OFF_PRED  30756   // 33
#define OFF_BA    30792   // 8
#define OFF_BB    30800
#define OFF_BC    30808
#define OFF_B1R   30816   // 2
#define OFF_B2S   30820   // 33
#define SMEM_FLOATS 30856

__global__ void __launch_bounds__(TPB, 1)
speller_kernel(const float* __restrict__ embed_g,
               const float* __restrict__ Wih0,
               const float* __restrict__ Wihr,
               const float* __restrict__ Whh,
               const float* __restrict__ bih,
               const float* __restrict__ bhh,
               const float* __restrict__ W1,
               const float* __restrict__ b1,
               const float* __restrict__ W2,
               const float* __restrict__ b2,
               const float* __restrict__ h0in,
               const float* __restrict__ c0in,
               float* __restrict__ out)
{
    extern __shared__ float sm[];
    float* l0w  = sm + OFF_L0W;
    float* wh1  = sm + OFF_WH1;
    float* wh2  = sm + OFF_WH2;
    float* wi1  = sm + OFF_WI1;
    float* wi2  = sm + OFF_WI2;
    float* w1r  = sm + OFF_W1R;
    float* w2s  = sm + OFF_W2S;
    float* embs = sm + OFF_EMB;
    float* h0s  = sm + OFF_H0S;
    float* h1s  = sm + OFF_H1S;
    float* h2s  = sm + OFF_H2S;
    float* rs   = sm + OFF_RS;
    float* gA   = sm + OFF_GA;
    float* gB   = sm + OFF_GB;
    float* gC   = sm + OFF_GC;
    float* gT   = sm + OFF_GT;
    float* gD   = sm + OFF_GD;
    float* pred = sm + OFF_PRED;
    float* biasA = sm + OFF_BA;
    float* biasB = sm + OFF_BB;
    float* biasC = sm + OFF_BC;
    float* b1r  = sm + OFF_B1R;
    float* b2s  = sm + OFF_B2S;

    const int tid  = threadIdx.x;
    const int wid  = tid >> 5;
    const int lane = tid & 31;
    const int k    = blockIdx.x;
    const int j0   = 2 * k;          // this CTA's hidden-unit pair

    // ---- One-time weight staging (ctx columns are all-zero inputs: dropped) ----
    for (int idx = tid; idx < 8 * 512; idx += TPB) {
        int r = idx >> 9, c = idx & 511;
        int row = ((r >> 1) << 8) + j0 + (r & 1);        // gate*256 + unit
        l0w[idx] = (c < 256) ? Wih0[row * 384 + c] : Whh[row * 256 + (c - 256)];
    }
    for (int idx = tid; idx < 8 * 256; idx += TPB) {
        int r = idx >> 8, c = idx & 255;
        int row = ((r >> 1) << 8) + j0 + (r & 1);
        wh1[idx] = Whh[(1024 + row) * 256 + c];
        wh2[idx] = Whh[(2048 + row) * 256 + c];
        wi1[idx] = Wihr[row * 256 + c];
        wi2[idx] = Wihr[(1024 + row) * 256 + c];
    }
    for (int idx = tid; idx < 512; idx += TPB) {
        int u = idx >> 8, c = idx & 255;
        w1r[idx] = W1[(j0 + u) * 384 + c];
    }
    for (int idx = tid; idx < 33 * 256; idx += TPB) {
        w2s[idx]  = W2[idx];
        embs[idx] = embed_g[idx];
    }
    for (int idx = tid; idx < 256; idx += TPB) {
        h0s[idx] = h0in[idx];
        h1s[idx] = h0in[256 + idx];
        h2s[idx] = h0in[512 + idx];
    }
    if (tid < 8) {
        int row = ((tid >> 1) << 8) + j0 + (tid & 1);
        biasA[tid] = bih[row] + bhh[row];
        biasB[tid] = bih[1024 + row] + bhh[1024 + row];
        biasC[tid] = bih[2048 + row] + bhh[2048 + row];
    }
    if (tid < 2)  b1r[tid] = b1[j0 + tid];
    if (tid < 33) b2s[tid] = b2[tid];

    float cA = 0.f, cB = 0.f, cC = 0.f;     // cell states live in warp0 lanes 0,1
    if (tid < 2) {
        cA = c0in[j0 + tid];
        cB = c0in[256 + j0 + tid];
        cC = c0in[512 + j0 + tid];
    }
    int ch = 0;                              // greedy char (uniform across CTAs)
    __syncthreads();

    for (int t = 0; t < T_STEPS; t++) {
        const unsigned seq = (unsigned)(t + 1);

        // ===== Phase A: layer0 gates + Whh1*h1 / Whh2*h2 partials (no wait) =====
        {
            const float4* wr4 = (const float4*)(l0w + wid * 512);
            const float4* xe4 = (const float4*)(embs + ch * 256);
            const float4* h04 = (const float4*)h0s;
            float s = 0.f;
#pragma unroll
            for (int i = 0; i < 2; i++) {
                float4 a = wr4[i * 32 + lane], b = xe4[i * 32 + lane];
                s += a.x * b.x + a.y * b.y + a.z * b.z + a.w * b.w;
            }
#pragma unroll
            for (int i = 0; i < 2; i++) {
                float4 a = wr4[(i + 2) * 32 + lane], b = h04[i * 32 + lane];
                s += a.x * b.x + a.y * b.y + a.z * b.z + a.w * b.w;
            }
            float s1 = dot256(wh1 + wid * 256, h1s, lane);
            float s2 = dot256(wh2 + wid * 256, h2s, lane);
            s  = wreduce(s);
            s1 = wreduce(s1);
            s2 = wreduce(s2);
            if (lane == 0) {
                float g0 = s + biasA[wid];
                gA[wid] = (wid >= 4 && wid < 6) ? tanhf(g0) : sigf(g0);
                gB[wid] = s1 + biasB[wid];   // raw partial, bias folded
                gC[wid] = s2 + biasC[wid];
            }
        }
        __syncthreads();
        if (wid == 0) {
            float h = 0.f;
            if (lane < 2) {
                cA = gA[2 + lane] * cA + gA[lane] * gA[4 + lane];
                h  = gA[6 + lane] * tanhf(cA);
            }
            float ha = __shfl_sync(0xffffffffu, h, 0);
            float hb = __shfl_sync(0xffffffffu, h, 1);
            if (lane == 0) stv4(&g_h0buf[k], ha, hb, seq);
        }

        // ===== Phase B: wait all h0, layer1 gates =====
        gather(g_h0buf, h0s, seq, wid, lane);
        {
            float s = wreduce(dot256(wi1 + wid * 256, h0s, lane));
            if (lane == 0) {
                float g = s + gB[wid];
                gT[wid] = (wid >= 4 && wid < 6) ? tanhf(g) : sigf(g);
            }
        }
        __syncthreads();
        if (wid == 0) {
            float h = 0.f;
            if (lane < 2) {
                cB = gT[2 + lane] * cB + gT[lane] * gT[4 + lane];
                h  = gT[6 + lane] * tanhf(cB);
            }
            float ha = __shfl_sync(0xffffffffu, h, 0);
            float hb = __shfl_sync(0xffffffffu, h, 1);
            if (lane == 0) stv4(&g_h1buf[k], ha, hb, seq);
        }

        // ===== Phase C: wait all h1, layer2 gates =====
        gather(g_h1buf, h1s, seq, wid, lane);
        {
            float s = wreduce(dot256(wi2 + wid * 256, h1s, lane));
            if (lane == 0) {
                float g = s + gC[wid];
                gT[wid] = (wid >= 4 && wid < 6) ? tanhf(g) : sigf(g);
            }
        }
        __syncthreads();
        if (wid == 0) {
            float h = 0.f;
            if (lane < 2) {
                cC = gT[2 + lane] * cC + gT[lane] * gT[4 + lane];
                h  = gT[6 + lane] * tanhf(cC);
            }
            float ha = __shfl_sync(0xffffffffu, h, 0);
            float hb = __shfl_sync(0xffffffffu, h, 1);
            if (lane == 0) stv4(&g_h2buf[k], ha, hb, seq);
        }

        // ===== Phase D: wait all h2, my 2 rows of r = relu(W1*h2 + b1) =====
        gather(g_h2buf, h2s, seq, wid, lane);
        if (wid < 2) {
            float s = wreduce(dot256(w1r + wid * 256, h2s, lane));
            if (lane == 0) gD[wid] = fmaxf(s + b1r[wid], 0.f);
        }
        __syncthreads();
        if (tid == 0) stv4(&g_rbuf[k], gD[0], gD[1], seq);

        // ===== Phase E: wait all r, redundant classifier + argmax + output =====
        gather(g_rbuf, rs, seq, wid, lane);
        for (int v = wid; v < 33; v += 8) {
            float s = wreduce(dot256(w2s + v * 256, rs, lane));
            if (lane == 0) pred[v] = s + b2s[v];
        }
        __syncthreads();
        {
            float best = pred[0];
            int bi = 0;
#pragma unroll
            for (int v = 1; v < 33; v++) {
                float p = pred[v];
                if (p > best) { best = p; bi = v; }
            }
            ch = bi;   // bit-identical in every CTA -> uniform feedback
        }
        // write this CTA's 8 identical batch rows: out[b, t, 0:33]
        for (int idx = tid; idx < 8 * 33; idx += TPB) {
            int bl = idx / 33, v = idx - bl * 33;
            out[((size_t)(j0 * 4 + bl) * T_STEPS + t) * 33 + v] = pred[v];
        }
        // no extra sync needed: next phase-A writes/reads are fenced by the
        // post-A __syncthreads and the gather syncs before any smem reuse.
    }
}

extern "C" void kernel_launch(void* const* d_in, const int* in_sizes, int n_in,
                              void* d_out, int out_size) {
    // metadata order: labels, embed, Wih0, Wih_rest, Whh, bih, bhh,
    //                 W1, b1, W2, b2, h0, c0
    const float* embed = (const float*)d_in[1];
    const float* Wih0  = (const float*)d_in[2];
    const float* Wihr  = (const float*)d_in[3];
    const float* Whh   = (const float*)d_in[4];
    const float* bih   = (const float*)d_in[5];
    const float* bhh   = (const float*)d_in[6];
    const float* W1    = (const float*)d_in[7];
    const float* b1    = (const float*)d_in[8];
    const float* W2    = (const float*)d_in[9];
    const float* b2    = (const float*)d_in[10];
    const float* h0    = (const float*)d_in[11];
    const float* c0    = (const float*)d_in[12];
    float* out = (float*)d_out;

    size_t smem = (size_t)SMEM_FLOATS * sizeof(float);
    static bool attr_set = false;
    if (!attr_set) {
        cudaFuncSetAttribute(speller_kernel,
                             cudaFuncAttributeMaxDynamicSharedMemorySize,
                             (int)smem);
        attr_set = true;
    }
    speller_kernel<<<G, TPB, smem>>>(embed, Wih0, Wihr, Whh, bih, bhh,
                                     W1, b1, W2, b2, h0, c0, out);
}

// round 6
// speedup vs baseline: 2.9778x; 2.9778x over previous
#include <cuda_runtime.h>

#define G 128
#define TPB 256
#define T_STEPS 220
#define SLOT_STRIDE 16   // float4s per slot: 256B -> spreads L2 slice hash bits

// Seqlock exchange buffers: {val0, val1, seq, seq} per CTA, 256B-strided to
// avoid LTS slice hotspotting (bits 8,10-14 vary across slots).
__device__ float4 g_h0buf[G * SLOT_STRIDE];
__device__ float4 g_h1buf[G * SLOT_STRIDE];
__device__ float4 g_h2buf[G * SLOT_STRIDE];
__device__ float4 g_rbuf [G * SLOT_STRIDE];

__device__ __forceinline__ void ldv4(const float4* p, float& a, float& b,
                                     unsigned& s0, unsigned& s1) {
    unsigned x, y;
    asm volatile("ld.volatile.global.v4.b32 {%0,%1,%2,%3}, [%4];"
                 : "=r"(x), "=r"(y), "=r"(s0), "=r"(s1) : "l"(p));
    a = __uint_as_float(x);
    b = __uint_as_float(y);
}
__device__ __forceinline__ void stv4(float4* p, float a, float b, unsigned s) {
    asm volatile("st.volatile.global.v4.b32 [%0], {%1,%2,%3,%4};"
                 :: "l"(p), "r"(__float_as_uint(a)), "r"(__float_as_uint(b)),
                    "r"(s), "r"(s));
}
__device__ __forceinline__ float wreduce(float v) {
    v += __shfl_xor_sync(0xffffffffu, v, 16);
    v += __shfl_xor_sync(0xffffffffu, v, 8);
    v += __shfl_xor_sync(0xffffffffu, v, 4);
    v += __shfl_xor_sync(0xffffffffu, v, 2);
    v += __shfl_xor_sync(0xffffffffu, v, 1);
    return v;
}
// Fast activations (~1e-6 rel err; logit gaps ~1e-2, argmax-safe)
__device__ __forceinline__ float fsig(float x) {
    return __fdividef(1.0f, 1.0f + __expf(-x));
}
__device__ __forceinline__ float ftanh(float x) {
    return 1.0f - __fdividef(2.0f, __expf(2.0f * x) + 1.0f);
}
__device__ __forceinline__ float dot256(const float* w, const float* x, int lane) {
    const float4* w4 = (const float4*)w;
    const float4* x4 = (const float4*)x;
    float s = 0.f;
#pragma unroll
    for (int i = 0; i < 2; i++) {
        float4 a = w4[i * 32 + lane], b = x4[i * 32 + lane];
        s += a.x * b.x + a.y * b.y + a.z * b.z + a.w * b.w;
    }
    return s;
}
// Warps 0-3 poll all 128 strided slices (one 16B load/lane), scatter to SMEM.
__device__ __forceinline__ void gather(const float4* buf, float* dst,
                                       unsigned seq, int wid, int lane) {
    if (wid < 4) {
        int s = wid * 32 + lane;
        const float4* p = buf + (size_t)s * SLOT_STRIDE;
        float a, b; unsigned s0, s1;
        for (;;) {
            ldv4(p, a, b, s0, s1);
            if (__all_sync(0xffffffffu, (s0 == seq) & (s1 == seq))) break;
        }
        dst[2 * s] = a;
        dst[2 * s + 1] = b;
    }
    __syncthreads();
}

// SMEM layout (floats)
#define OFF_L0W   0       // 8 x 512  layer0 [Wih(:,0:256) | Whh]
#define OFF_WH1   4096    // 8 x 256
#define OFF_WH2   6144    // 8 x 256
#define OFF_WI1   8192    // 8 x 256
#define OFF_WI2   10240   // 8 x 256
#define OFF_W1R   12288   // 2 x 256
#define OFF_W2S   12800   // 33 x 256
#define OFF_EMB   21248   // 33 x 256
#define OFF_H0S   29696   // 256
#define OFF_H1S   29952
#define OFF_H2S   30208
#define OFF_RS    30464
#define OFF_GT    30720   // 8 current-layer gates
#define OFF_PA    30728   // 8 precomputed layer0 partials (+bias)
#define OFF_PB    30736   // 8 layer1 Whh partials (+bias)
#define OFF_PC    30744   // 8 layer2 Whh partials (+bias)
#define OFF_PRED  30752   // 33
#define OFF_BA    30788   // 8
#define OFF_BB    30796
#define OFF_BC    30804
#define OFF_B1R   30812   // 2
#define OFF_B2S   30816   // 33
#define SMEM_FLOATS 30852

__global__ void __launch_bounds__(TPB, 1)
speller_kernel(const float* __restrict__ embed_g,
               const float* __restrict__ Wih0,
               const float* __restrict__ Wihr,
               const float* __restrict__ Whh,
               const float* __restrict__ bih,
               const float* __restrict__ bhh,
               const float* __restrict__ W1,
               const float* __restrict__ b1,
               const float* __restrict__ W2,
               const float* __restrict__ b2,
               const float* __restrict__ h0in,
               const float* __restrict__ c0in,
               float* __restrict__ out)
{
    extern __shared__ float sm[];
    float* l0w  = sm + OFF_L0W;
    float* wh1  = sm + OFF_WH1;
    float* wh2  = sm + OFF_WH2;
    float* wi1  = sm + OFF_WI1;
    float* wi2  = sm + OFF_WI2;
    float* w1r  = sm + OFF_W1R;
    float* w2s  = sm + OFF_W2S;
    float* embs = sm + OFF_EMB;
    float* h0s  = sm + OFF_H0S;
    float* h1s  = sm + OFF_H1S;
    float* h2s  = sm + OFF_H2S;
    float* rs   = sm + OFF_RS;
    float* gT   = sm + OFF_GT;
    float* pA   = sm + OFF_PA;
    float* pB   = sm + OFF_PB;
    float* pC   = sm + OFF_PC;
    float* pred = sm + OFF_PRED;
    float* biasA = sm + OFF_BA;
    float* biasB = sm + OFF_BB;
    float* biasC = sm + OFF_BC;
    float* b1r  = sm + OFF_B1R;
    float* b2s  = sm + OFF_B2S;

    const int tid  = threadIdx.x;
    const int wid  = tid >> 5;
    const int lane = tid & 31;
    const int k    = blockIdx.x;
    const int j0   = 2 * k;          // this CTA's hidden-unit pair

    // ---- One-time weight staging (ctx columns are all-zero: dropped) ----
    for (int idx = tid; idx < 8 * 512; idx += TPB) {
        int r = idx >> 9, c = idx & 511;
        int row = ((r >> 1) << 8) + j0 + (r & 1);        // gate*256 + unit
        l0w[idx] = (c < 256) ? Wih0[row * 384 + c] : Whh[row * 256 + (c - 256)];
    }
    for (int idx = tid; idx < 8 * 256; idx += TPB) {
        int r = idx >> 8, c = idx & 255;
        int row = ((r >> 1) << 8) + j0 + (r & 1);
        wh1[idx] = Whh[(1024 + row) * 256 + c];
        wh2[idx] = Whh[(2048 + row) * 256 + c];
        wi1[idx] = Wihr[row * 256 + c];
        wi2[idx] = Wihr[(1024 + row) * 256 + c];
    }
    for (int idx = tid; idx < 512; idx += TPB) {
        int u = idx >> 8, c = idx & 255;
        w1r[idx] = W1[(j0 + u) * 384 + c];
    }
    for (int idx = tid; idx < 33 * 256; idx += TPB) {
        w2s[idx]  = W2[idx];
        embs[idx] = embed_g[idx];
    }
    for (int idx = tid; idx < 256; idx += TPB) {
        h0s[idx] = h0in[idx];
        h1s[idx] = h0in[256 + idx];
        h2s[idx] = h0in[512 + idx];
    }
    if (tid < 8) {
        int row = ((tid >> 1) << 8) + j0 + (tid & 1);
        biasA[tid] = bih[row] + bhh[row];
        biasB[tid] = bih[1024 + row] + bhh[1024 + row];
        biasC[tid] = bih[2048 + row] + bhh[2048 + row];
    }
    if (tid < 2)  b1r[tid] = b1[j0 + tid];
    if (tid < 33) b2s[tid] = b2[tid];

    float cA = 0.f, cB = 0.f, cC = 0.f;     // cell states in warp0 lanes 0,1
    if (tid < 2) {
        cA = c0in[j0 + tid];
        cB = c0in[256 + j0 + tid];
        cC = c0in[512 + j0 + tid];
    }
    int ch = 0;
    __syncthreads();

    // ---- Initial recurrent partials from h(t=0) ----
    {
        float s0 = dot256(l0w + wid * 512 + 256, h0s, lane);
        float s1 = dot256(wh1 + wid * 256, h1s, lane);
        float s2 = dot256(wh2 + wid * 256, h2s, lane);
        s0 = wreduce(s0); s1 = wreduce(s1); s2 = wreduce(s2);
        if (lane == 0) {
            pA[wid] = s0 + biasA[wid];
            pB[wid] = s1 + biasB[wid];
            pC[wid] = s2 + biasC[wid];
        }
    }
    __syncthreads();

    for (int t = 0; t < T_STEPS; t++) {
        const unsigned seq = (unsigned)(t + 1);

        // ===== Phase A (lite): embed dot + precomputed recurrent partial =====
        {
            float s = wreduce(dot256(l0w + wid * 512, embs + ch * 256, lane));
            if (lane == 0) {
                float g = s + pA[wid];
                gT[wid] = (wid == 4 || wid == 5) ? ftanh(g) : fsig(g);
            }
        }
        __syncthreads();
        if (wid == 0) {
            float h = 0.f;
            if (lane < 2) {
                cA = gT[2 + lane] * cA + gT[lane] * gT[4 + lane];
                h  = gT[6 + lane] * ftanh(cA);
            }
            float ha = __shfl_sync(0xffffffffu, h, 0);
            float hb = __shfl_sync(0xffffffffu, h, 1);
            if (lane == 0) stv4(&g_h0buf[k * SLOT_STRIDE], ha, hb, seq);
        }

        // ===== Phase B: wait all h0, layer1 gates =====
        gather(g_h0buf, h0s, seq, wid, lane);
        {
            float s = wreduce(dot256(wi1 + wid * 256, h0s, lane));
            if (lane == 0) {
                float g = s + pB[wid];
                gT[wid] = (wid == 4 || wid == 5) ? ftanh(g) : fsig(g);
            }
        }
        __syncthreads();
        if (wid == 0) {
            float h = 0.f;
            if (lane < 2) {
                cB = gT[2 + lane] * cB + gT[lane] * gT[4 + lane];
                h  = gT[6 + lane] * ftanh(cB);
            }
            float ha = __shfl_sync(0xffffffffu, h, 0);
            float hb = __shfl_sync(0xffffffffu, h, 1);
            if (lane == 0) stv4(&g_h1buf[k * SLOT_STRIDE], ha, hb, seq);
        }

        // ===== Phase C: wait all h1, layer2 gates =====
        gather(g_h1buf, h1s, seq, wid, lane);
        {
            float s = wreduce(dot256(wi2 + wid * 256, h1s, lane));
            if (lane == 0) {
                float g = s + pC[wid];
                gT[wid] = (wid == 4 || wid == 5) ? ftanh(g) : fsig(g);
            }
        }
        __syncthreads();
        if (wid == 0) {
            float h = 0.f;
            if (lane < 2) {
                cC = gT[2 + lane] * cC + gT[lane] * gT[4 + lane];
                h  = gT[6 + lane] * ftanh(cC);
            }
            float ha = __shfl_sync(0xffffffffu, h, 0);
            float hb = __shfl_sync(0xffffffffu, h, 1);
            if (lane == 0) stv4(&g_h2buf[k * SLOT_STRIDE], ha, hb, seq);
        }

        // ===== Phase D: wait all h2; warp0 publishes both r rows (no bar) =====
        gather(g_h2buf, h2s, seq, wid, lane);
        if (wid == 0) {
            float s0 = dot256(w1r, h2s, lane);
            float s1 = dot256(w1r + 256, h2s, lane);
            s0 = wreduce(s0); s1 = wreduce(s1);
            if (lane == 0) {
                float r0 = fmaxf(s0 + b1r[0], 0.f);
                float r1 = fmaxf(s1 + b1r[1], 0.f);
                stv4(&g_rbuf[k * SLOT_STRIDE], r0, r1, seq);
            }
        }
        // Overlap: next step's recurrent partials (h0s/h1s/h2s = step-t values)
        {
            float s0 = dot256(l0w + wid * 512 + 256, h0s, lane);
            float s1 = dot256(wh1 + wid * 256, h1s, lane);
            float s2 = dot256(wh2 + wid * 256, h2s, lane);
            s0 = wreduce(s0); s1 = wreduce(s1); s2 = wreduce(s2);
            if (lane == 0) {
                pA[wid] = s0 + biasA[wid];
                pB[wid] = s1 + biasB[wid];
                pC[wid] = s2 + biasC[wid];
            }
        }

        // ===== Phase E: wait all r, redundant classifier + argmax + output =====
        gather(g_rbuf, rs, seq, wid, lane);
        {
            float s0 = dot256(w2s + wid * 256, rs, lane);
            float s1 = dot256(w2s + (wid + 8) * 256, rs, lane);
            float s2 = dot256(w2s + (wid + 16) * 256, rs, lane);
            float s3 = dot256(w2s + (wid + 24) * 256, rs, lane);
            s0 = wreduce(s0); s1 = wreduce(s1);
            s2 = wreduce(s2); s3 = wreduce(s3);
            if (lane == 0) {
                pred[wid]      = s0 + b2s[wid];
                pred[wid + 8]  = s1 + b2s[wid + 8];
                pred[wid + 16] = s2 + b2s[wid + 16];
                pred[wid + 24] = s3 + b2s[wid + 24];
            }
            if (wid == 0) {
                float s4 = wreduce(dot256(w2s + 32 * 256, rs, lane));
                if (lane == 0) pred[32] = s4 + b2s[32];
            }
        }
        __syncthreads();
        {
            float best = pred[0];
            int bi = 0;
#pragma unroll
            for (int v = 1; v < 33; v++) {
                float p = pred[v];
                if (p > best) { best = p; bi = v; }
            }
            ch = bi;   // bit-identical in every CTA -> uniform feedback
        }
        // write this CTA's 8 identical batch rows: out[b, t, 0:33]
        for (int idx = tid; idx < 8 * 33; idx += TPB) {
            int bl = idx / 33, v = idx - bl * 33;
            out[((size_t)(j0 * 4 + bl) * T_STEPS + t) * 33 + v] = pred[v];
        }
        // Reuse safety: pred/rs/h*s/p* next overwritten only after multiple
        // intervening __syncthreads + global phase waits (see phase ordering).
    }
}

extern "C" void kernel_launch(void* const* d_in, const int* in_sizes, int n_in,
                              void* d_out, int out_size) {
    // metadata order: labels, embed, Wih0, Wih_rest, Whh, bih, bhh,
    //                 W1, b1, W2, b2, h0, c0
    const float* embed = (const float*)d_in[1];
    const float* Wih0  = (const float*)d_in[2];
    const float* Wihr  = (const float*)d_in[3];
    const float* Whh   = (const float*)d_in[4];
    const float* bih   = (const float*)d_in[5];
    const float* bhh   = (const float*)d_in[6];
    const float* W1    = (const float*)d_in[7];
    const float* b1    = (const float*)d_in[8];
    const float* W2    = (const float*)d_in[9];
    const float* b2    = (const float*)d_in[10];
    const float* h0    = (const float*)d_in[11];
    const float* c0    = (const float*)d_in[12];
    float* out = (float*)d_out;

    size_t smem = (size_t)SMEM_FLOATS * sizeof(float);
    cudaFuncSetAttribute(speller_kernel,
                         cudaFuncAttributeMaxDynamicSharedMemorySize,
                         (int)smem);
    speller_kernel<<<G, TPB, smem>>>(embed, Wih0, Wihr, Whh, bih, bhh,
                                     W1, b1, W2, b2, h0, c0, out);
}